// round 11
// baseline (speedup 1.0000x reference)
#include <cuda_runtime.h>
#include <math.h>
#include <stdint.h>

#define NPTS 131072
#define NC 4096
#define MAXPASS 8192
#define NBLK 1776          // 12 blocks/SM x 148 SMs, persistent

// ring-buffer float offsets for streamed layers
#define OFF1 0
#define OFF2 2016
#define OFF3 0
#define OFF4 1024
#define OFF5 2912
#define BUFN 3168

typedef unsigned long long u64;

// ---------------- scratch (device globals) ----------------------------------
__device__ int g_cell_of[NPTS];
__device__ float4 g_pt[2 * NPTS];     // (x0,x1,x2,d0),(d1,d2,idx,-) per sorted slot
__device__ int g_count[NC];
__device__ int g_start[NC + 1];
__device__ int g_cursor[NC];
__device__ int g_npass;
__device__ int g_fetch;
__device__ int2 g_pass[MAXPASS];      // x = slot start, y = cell | (len<<16), len<=64
__device__ float g_w2pad[NC * 32 * 36];   // w2 rows padded 33 -> 36
__device__ float g_w5pad[NC * 32 * 4];    // w5 rows padded 3 -> 4

__device__ __forceinline__ int cell_coord(float v) {
    float f = v / 0.1875f + 8.0f;
    int c = (int)f;
    if (c < 0) c = 0;
    if (c > 15) c = 15;
    return c;
}

// ------ pass 1 (fused): histogram blocks + weight-padding blocks ------------
#define HIST_B (NPTS / 256)                       // 512
#define PAD2_T (NC * 1056)
#define PAD5_T (NC * 96)
#define PAD_B ((PAD2_T + PAD5_T + 255) / 256)
__global__ void k_hist_pad(const float* __restrict__ x,
                           const float* __restrict__ w2,
                           const float* __restrict__ w5) {
    int b = blockIdx.x;
    if (b < HIST_B) {
        int p = b * 256 + threadIdx.x;
        float x0 = x[3 * p + 0], x1 = x[3 * p + 1], x2 = x[3 * p + 2];
        if (!((fabsf(x0) < 1.5f) && (fabsf(x1) < 1.5f) && (fabsf(x2) < 1.5f))) return;
        int c0 = cell_coord(x0);
        int c1 = cell_coord(x1);
        int c2 = cell_coord(x2);
        int cell = (c0 * 16 + c1) * 16 + c2;
        g_cell_of[p] = cell;
        atomicAdd(&g_count[cell], 1);
    } else {
        int t = (b - HIST_B) * 256 + threadIdx.x;
        if (t < PAD2_T) {
            int cell = t / 1056;
            int i = t - cell * 1056;
            int r = i / 33, c = i - r * 33;
            g_w2pad[cell * 1152 + r * 36 + c] = w2[t];
        } else if (t < PAD2_T + PAD5_T) {
            int u = t - PAD2_T;
            int cell = u / 96;
            int i = u - cell * 96;
            int r = i / 3, c = i - r * 3;
            g_w5pad[cell * 128 + r * 4 + c] = w5[u];
        }
    }
}

// ------ pass 2: shfl-scan + reset counts + build pass list (1 block) --------
__global__ void k_scan() {
    __shared__ int wsum[32];
    int t = threadIdx.x;
    int lane = t & 31, w = t >> 5;
    if (t == 0) { g_npass = 0; g_fetch = 0; }
    int b = t * 4;
    int4 cv = *(int4*)&g_count[b];
    *(int4*)&g_count[b] = make_int4(0, 0, 0, 0);
    int sum = cv.x + cv.y + cv.z + cv.w;
    int inc = sum;
    #pragma unroll
    for (int o = 1; o < 32; o <<= 1) {
        int v = __shfl_up_sync(0xFFFFFFFFu, inc, o);
        if (lane >= o) inc += v;
    }
    if (lane == 31) wsum[w] = inc;
    __syncthreads();
    if (w == 0) {
        int v = wsum[lane];
        int i = v;
        #pragma unroll
        for (int o = 1; o < 32; o <<= 1) {
            int u = __shfl_up_sync(0xFFFFFFFFu, i, o);
            if (lane >= o) i += u;
        }
        wsum[lane] = i - v;   // exclusive
    }
    __syncthreads();
    int excl = wsum[w] + inc - sum;
    int st[5];
    st[0] = excl;
    st[1] = excl + cv.x;
    st[2] = excl + cv.x + cv.y;
    st[3] = excl + cv.x + cv.y + cv.z;
    st[4] = excl + sum;
    g_start[b + 0] = st[0];
    g_start[b + 1] = st[1];
    g_start[b + 2] = st[2];
    g_start[b + 3] = st[3];
    if (t == 1023) g_start[NC] = st[4];

    // build 64-point pass list for this thread's 4 cells
    #pragma unroll
    for (int k = 0; k < 4; k++) {
        int c = b + k;
        g_cursor[c] = 0;
        int s = st[k];
        int cnt = st[k + 1] - s;
        if (cnt == 0) continue;
        int np = (cnt + 63) >> 6;
        int base = atomicAdd(&g_npass, np);
        for (int j = 0; j < np; j++) {
            int len = min(64, cnt - 64 * j);
            g_pass[base + j] = make_int2(s + 64 * j, c | (len << 16));
        }
    }
}

// ---------------- pass 3: scatter staged data / zero masked outputs ---------
__global__ void k_scatter(const float* __restrict__ x, const float* __restrict__ d,
                          float* __restrict__ out) {
    int p = blockIdx.x * blockDim.x + threadIdx.x;
    if (p >= NPTS) return;
    float x0 = x[3 * p + 0], x1 = x[3 * p + 1], x2 = x[3 * p + 2];
    bool mask = (fabsf(x0) < 1.5f) && (fabsf(x1) < 1.5f) && (fabsf(x2) < 1.5f);
    if (!mask) {
        out[3 * p + 0] = 0.0f;
        out[3 * p + 1] = 0.0f;
        out[3 * p + 2] = 0.0f;
        out[3 * NPTS + p] = 0.0f;
        return;
    }
    int cell = g_cell_of[p];
    int pos = g_start[cell] + atomicAdd(&g_cursor[cell], 1);
    float d0 = d[3 * p + 0], d1 = d[3 * p + 1], d2 = d[3 * p + 2];
    g_pt[2 * pos + 0] = make_float4(x0, x1, x2, d0);
    g_pt[2 * pos + 1] = make_float4(d1, d2, __int_as_float(p), 0.0f);
}

// ---------------- fast sincos: Cody-Waite reduction + MUFU ------------------
__device__ __forceinline__ void fsincos(float a, float& sn, float& cs) {
    float k = rintf(a * 0.15915493667125702f);
    float r = fmaf(k, -6.2831854820251465f, a);
    r = fmaf(k, 1.7484556000744487e-7f, r);
    sn = __sinf(r);
    cs = __cosf(r);
}

// ---------------- cp.async helpers ------------------------------------------
__device__ __forceinline__ void cpa16(uint32_t saddr, const void* g) {
    asm volatile("cp.async.cg.shared.global [%0], [%1], 16;" :: "r"(saddr), "l"(g));
}
__device__ __forceinline__ void cpa_commit() {
    asm volatile("cp.async.commit_group;");
}
__device__ __forceinline__ void cpa_wait0() {
    asm volatile("cp.async.wait_group 0;");
}
__device__ __forceinline__ void cpa_wait1() {
    asm volatile("cp.async.wait_group 1;");
}

template <int N4>
__device__ __forceinline__ void stage(uint32_t dst, const float4* __restrict__ src, int tid) {
    #pragma unroll
    for (int i = tid; i < N4; i += 32) cpa16(dst + 16u * i, src + i);
}

// ---------------- packed f32x2 primitives -----------------------------------
__device__ __forceinline__ void fma2(u64& a, u64 v, u64 w) {
    asm("fma.rn.f32x2 %0, %1, %2, %0;" : "+l"(a) : "l"(v), "l"(w));
}
__device__ __forceinline__ u64 pk2(float v) {
    u64 r; asm("mov.b64 %0, {%1, %1};" : "=l"(r) : "f"(v)); return r;
}
__device__ __forceinline__ float2 upk(u64 p) {
    float2 f; asm("mov.b64 {%0, %1}, %2;" : "=f"(f.x), "=f"(f.y) : "l"(p)); return f;
}

// feed two points' scalars through one weight row (weights loaded ONCE)
template <int NP2>
__device__ __forceinline__ void feedp2(float v0, float v1,
                                       const float* __restrict__ w,
                                       u64* a0, u64* a1) {
    u64 vv0 = pk2(v0), vv1 = pk2(v1);
    const ulonglong2* wv = (const ulonglong2*)w;
    #pragma unroll
    for (int k = 0; k < NP2; k++) {
        ulonglong2 u = wv[k];
        fma2(a0[2 * k + 0], vv0, u.x);
        fma2(a0[2 * k + 1], vv0, u.y);
        fma2(a1[2 * k + 0], vv1, u.x);
        fma2(a1[2 * k + 1], vv1, u.y);
    }
}

// ------- pass 4: persistent blocks, work-steal one 64-point pass at a time --
__global__ void __launch_bounds__(32, 12) k_mlp(
    const float* __restrict__ w1, const float* __restrict__ b1,
    const float* __restrict__ b2,
    const float* __restrict__ w3, const float* __restrict__ b3,
    const float* __restrict__ w4, const float* __restrict__ b4,
    const float* __restrict__ b5,
    float* __restrict__ out)
{
    int tid = threadIdx.x;

    __shared__ __align__(16) float sbuf[BUFN];
    __shared__ __align__(16) float sb1[32];
    __shared__ __align__(16) float sb2[36];
    __shared__ __align__(16) float sb3[32];
    __shared__ __align__(16) float sb4[32];
    __shared__ __align__(16) float sb5[4];

    uint32_t sb = (uint32_t)__cvta_generic_to_shared(sbuf);
    int npass = g_npass;

    while (true) {
        int pid;
        if (tid == 0) pid = atomicAdd(&g_fetch, 1);
        pid = __shfl_sync(0xFFFFFFFFu, pid, 0);
        if (pid >= npass) break;

        int2 pe = g_pass[pid];
        int slot0 = pe.x;
        int cell = pe.y & 0xFFFF;
        int len = pe.y >> 16;

        const size_t c = (size_t)cell;
        const float4* w1v = (const float4*)(w1 + c * 2016);
        const float4* w2v = (const float4*)(g_w2pad + c * 1152);
        const float4* w3v = (const float4*)(w3 + c * 1024);
        const float4* w4v = (const float4*)(w4 + c * 1888);
        const float4* w5v = (const float4*)(g_w5pad + c * 128);

        // issue L1 and L2 prefetch immediately
        stage<504>(sb + OFF1 * 4, w1v, tid); cpa_commit();
        stage<288>(sb + OFF2 * 4, w2v, tid); cpa_commit();

        // biases (regular LDG/STS, overlap with cp.async)
        sb1[tid] = b1[c * 32 + tid];
        sb3[tid] = b3[c * 32 + tid];
        sb4[tid] = b4[c * 32 + tid];
        sb2[tid] = b2[c * 33 + tid];
        if (tid == 0) sb2[32] = b2[c * 33 + 32];
        if (tid < 3) sb5[tid] = b5[c * 3 + tid];

        // two points per thread: q0 = tid, q1 = tid + 32
        bool act0 = tid < len;
        bool act1 = tid + 32 < len;
        int s0 = slot0 + (act0 ? tid : (len - 1));
        int s1 = slot0 + (act1 ? tid + 32 : (len - 1));
        float4 pa0 = g_pt[2 * s0 + 0];
        float4 pb0 = g_pt[2 * s0 + 1];
        float4 pa1 = g_pt[2 * s1 + 0];
        float4 pb1 = g_pt[2 * s1 + 1];
        float x00 = pa0.x, x01 = pa0.y, x02 = pa0.z;
        float d00 = pa0.w, d01 = pb0.x, d02 = pb0.y;
        int idx0 = __float_as_int(pb0.z);
        float x10 = pa1.x, x11 = pa1.y, x12 = pa1.z;
        float d10 = pa1.w, d11 = pb1.x, d12 = pb1.y;
        int idx1 = __float_as_int(pb1.z);

        cpa_wait1();
        __syncwarp();

        u64 P0[16], P1[16];         // packed accumulator pairs per point
        float A0[33], A1[33];       // activations per point

        // ---- layer 1: encode(x) [63] -> 32, relu ----
        {
            const float* sw1 = sbuf + OFF1;
            const u64* bp = (const u64*)sb1;
            #pragma unroll
            for (int k = 0; k < 16; k++) { P0[k] = bp[k]; P1[k] = bp[k]; }
            feedp2<8>(x00, x10, sw1 +  0, P0, P1);
            feedp2<8>(x01, x11, sw1 + 32, P0, P1);
            feedp2<8>(x02, x12, sw1 + 64, P0, P1);
            const float* wp = sw1 + 96;
            float s = 1.0f;
            #pragma unroll
            for (int j = 0; j < 10; j++) {
                float sa0, ca0, sa1, ca1, sa2, ca2;
                float ta0, ua0, ta1, ua1, ta2, ua2;
                fsincos(s * x00, sa0, ca0);
                fsincos(s * x01, sa1, ca1);
                fsincos(s * x02, sa2, ca2);
                fsincos(s * x10, ta0, ua0);
                fsincos(s * x11, ta1, ua1);
                fsincos(s * x12, ta2, ua2);
                feedp2<8>(sa0, ta0, wp, P0, P1); wp += 32;
                feedp2<8>(sa1, ta1, wp, P0, P1); wp += 32;
                feedp2<8>(sa2, ta2, wp, P0, P1); wp += 32;
                feedp2<8>(ca0, ua0, wp, P0, P1); wp += 32;
                feedp2<8>(ca1, ua1, wp, P0, P1); wp += 32;
                feedp2<8>(ca2, ua2, wp, P0, P1); wp += 32;
                s *= 2.0f;
            }
            #pragma unroll
            for (int k = 0; k < 16; k++) {
                float2 f0 = upk(P0[k]);
                float2 f1 = upk(P1[k]);
                A0[2 * k + 0] = fmaxf(f0.x, 0.0f);
                A0[2 * k + 1] = fmaxf(f0.y, 0.0f);
                A1[2 * k + 0] = fmaxf(f1.x, 0.0f);
                A1[2 * k + 1] = fmaxf(f1.y, 0.0f);
            }
        }

        cpa_wait0(); __syncwarp();
        stage<256>(sb + OFF3 * 4, w3v, tid); cpa_commit();   // prefetch L3

        // ---- layer 2: 32 -> 33 (rows padded to 36), relu; sigma = out[0] ----
        float sigma0, sigma1;
        {
            const float* sw2 = sbuf + OFF2;
            const u64* bp = (const u64*)sb2;
            #pragma unroll
            for (int k = 0; k < 16; k++) { P0[k] = bp[k]; P1[k] = bp[k]; }
            float a32_0 = sb2[32], a32_1 = a32_0;
            #pragma unroll
            for (int i = 0; i < 32; i++) {
                const float* row = sw2 + i * 36;
                feedp2<8>(A0[i], A1[i], row, P0, P1);
                float wlast = row[32];
                a32_0 = fmaf(A0[i], wlast, a32_0);
                a32_1 = fmaf(A1[i], wlast, a32_1);
            }
            #pragma unroll
            for (int k = 0; k < 16; k++) {
                float2 f0 = upk(P0[k]);
                float2 f1 = upk(P1[k]);
                A0[2 * k + 0] = fmaxf(f0.x, 0.0f);
                A0[2 * k + 1] = fmaxf(f0.y, 0.0f);
                A1[2 * k + 0] = fmaxf(f1.x, 0.0f);
                A1[2 * k + 1] = fmaxf(f1.y, 0.0f);
            }
            A0[32] = fmaxf(a32_0, 0.0f);
            A1[32] = fmaxf(a32_1, 0.0f);
            sigma0 = A0[0];
            sigma1 = A1[0];
        }

        cpa_wait0(); __syncwarp();
        stage<472>(sb + OFF4 * 4, w4v, tid); cpa_commit();   // prefetch L4

        // ---- layer 3: 32 -> 32, linear (inputs A[1..32]) ----
        {
            const float* sw3 = sbuf + OFF3;
            const u64* bp = (const u64*)sb3;
            #pragma unroll
            for (int k = 0; k < 16; k++) { P0[k] = bp[k]; P1[k] = bp[k]; }
            #pragma unroll
            for (int i = 0; i < 32; i++)
                feedp2<8>(A0[i + 1], A1[i + 1], sw3 + i * 32, P0, P1);
            #pragma unroll
            for (int k = 0; k < 16; k++) {
                float2 f0 = upk(P0[k]);
                float2 f1 = upk(P1[k]);
                A0[2 * k + 0] = f0.x;
                A0[2 * k + 1] = f0.y;
                A1[2 * k + 0] = f1.x;
                A1[2 * k + 1] = f1.y;
            }
        }

        cpa_wait0(); __syncwarp();
        stage<32>(sb + OFF5 * 4, w5v, tid); cpa_commit();    // prefetch L5

        // ---- layer 4: [32 | encode(d) 27] -> 32, relu ----
        {
            const float* sw4 = sbuf + OFF4;
            const u64* bp = (const u64*)sb4;
            #pragma unroll
            for (int k = 0; k < 16; k++) { P0[k] = bp[k]; P1[k] = bp[k]; }
            #pragma unroll
            for (int i = 0; i < 32; i++)
                feedp2<8>(A0[i], A1[i], sw4 + i * 32, P0, P1);
            const float* wp = sw4 + 32 * 32;
            feedp2<8>(d00, d10, wp, P0, P1); wp += 32;
            feedp2<8>(d01, d11, wp, P0, P1); wp += 32;
            feedp2<8>(d02, d12, wp, P0, P1); wp += 32;
            float s = 1.0f;
            #pragma unroll
            for (int j = 0; j < 4; j++) {
                float sa0, ca0, sa1, ca1, sa2, ca2;
                float ta0, ua0, ta1, ua1, ta2, ua2;
                fsincos(s * d00, sa0, ca0);
                fsincos(s * d01, sa1, ca1);
                fsincos(s * d02, sa2, ca2);
                fsincos(s * d10, ta0, ua0);
                fsincos(s * d11, ta1, ua1);
                fsincos(s * d12, ta2, ua2);
                feedp2<8>(sa0, ta0, wp, P0, P1); wp += 32;
                feedp2<8>(sa1, ta1, wp, P0, P1); wp += 32;
                feedp2<8>(sa2, ta2, wp, P0, P1); wp += 32;
                feedp2<8>(ca0, ua0, wp, P0, P1); wp += 32;
                feedp2<8>(ca1, ua1, wp, P0, P1); wp += 32;
                feedp2<8>(ca2, ua2, wp, P0, P1); wp += 32;
                s *= 2.0f;
            }
            #pragma unroll
            for (int k = 0; k < 16; k++) {
                float2 f0 = upk(P0[k]);
                float2 f1 = upk(P1[k]);
                A0[2 * k + 0] = fmaxf(f0.x, 0.0f);
                A0[2 * k + 1] = fmaxf(f0.y, 0.0f);
                A1[2 * k + 0] = fmaxf(f1.x, 0.0f);
                A1[2 * k + 1] = fmaxf(f1.y, 0.0f);
            }
        }

        cpa_wait0(); __syncwarp();

        // ---- layer 5: 32 -> 3 (rows padded to 4), sigmoid ----
        float r00, r01v, r02, r10, r11v, r12;
        {
            const float* sw5 = sbuf + OFF5;
            u64 p01_0, p01_1;
            asm("mov.b64 %0, {%1, %2};" : "=l"(p01_0) : "f"(sb5[0]), "f"(sb5[1]));
            p01_1 = p01_0;
            float r2_0 = sb5[2], r2_1 = r2_0;
            const ulonglong2* wv = (const ulonglong2*)sw5;
            #pragma unroll
            for (int i = 0; i < 32; i++) {
                ulonglong2 u = wv[i];
                fma2(p01_0, pk2(A0[i]), u.x);
                fma2(p01_1, pk2(A1[i]), u.x);
                float w2c = upk(u.y).x;
                r2_0 = fmaf(A0[i], w2c, r2_0);
                r2_1 = fmaf(A1[i], w2c, r2_1);
            }
            float2 f0 = upk(p01_0);
            float2 f1 = upk(p01_1);
            r00  = 1.0f / (1.0f + __expf(-f0.x));
            r01v = 1.0f / (1.0f + __expf(-f0.y));
            r02  = 1.0f / (1.0f + __expf(-r2_0));
            r10  = 1.0f / (1.0f + __expf(-f1.x));
            r11v = 1.0f / (1.0f + __expf(-f1.y));
            r12  = 1.0f / (1.0f + __expf(-r2_1));
        }

        if (act0) {
            out[3 * idx0 + 0] = r00;
            out[3 * idx0 + 1] = r01v;
            out[3 * idx0 + 2] = r02;
            out[3 * NPTS + idx0] = sigma0;
        }
        if (act1) {
            out[3 * idx1 + 0] = r10;
            out[3 * idx1 + 1] = r11v;
            out[3 * idx1 + 2] = r12;
            out[3 * NPTS + idx1] = sigma1;
        }
        __syncwarp();   // all lanes done reading sbuf before next pass restages
    }
}

// ---------------- launch ----------------------------------------------------
extern "C" void kernel_launch(void* const* d_in, const int* in_sizes, int n_in,
                              void* d_out, int out_size) {
    const float* x  = (const float*)d_in[0];
    const float* dd = (const float*)d_in[1];
    const float* w1 = (const float*)d_in[2];
    const float* b1 = (const float*)d_in[3];
    const float* w2 = (const float*)d_in[4];
    const float* b2 = (const float*)d_in[5];
    const float* w3 = (const float*)d_in[6];
    const float* b3 = (const float*)d_in[7];
    const float* w4 = (const float*)d_in[8];
    const float* b4 = (const float*)d_in[9];
    const float* w5 = (const float*)d_in[10];
    const float* b5 = (const float*)d_in[11];
    float* out = (float*)d_out;

    k_hist_pad<<<HIST_B + PAD_B, 256>>>(x, w2, w5);
    k_scan<<<1, 1024>>>();
    k_scatter<<<NPTS / 256, 256>>>(x, dd, out);
    k_mlp<<<NBLK, 32>>>(w1, b1, b2, w3, b3, w4, b4, b5, out);
}

// round 12
// speedup vs baseline: 1.3454x; 1.3454x over previous
#include <cuda_runtime.h>
#include <math.h>
#include <stdint.h>

#define NPTS 131072
#define NC 4096
#define MAXPASS 8192
#define NBLK 2368          // 16 blocks/SM x 148 SMs, persistent

// ring-buffer float offsets for streamed layers
#define OFF1 0
#define OFF2 2016
#define OFF3 0
#define OFF4 1024
#define OFF5 2912
#define BUFN 3168

typedef unsigned long long u64;

// ---------------- scratch (device globals) ----------------------------------
__device__ float4 g_pt[2 * NPTS];     // (x0,x1,x2,d0),(d1,d2,idx,-) per sorted slot
__device__ int g_count[NC];
__device__ int g_start[NC + 1];
__device__ int g_cursor[NC];
__device__ int g_npass;
__device__ int g_fetch;
__device__ int2 g_pass[MAXPASS];      // x = slot start, y = cell | (len<<16)

__device__ __forceinline__ int cell_coord(float v) {
    float f = v / 0.1875f + 8.0f;
    int c = (int)f;
    if (c < 0) c = 0;
    if (c > 15) c = 15;
    return c;
}
__device__ __forceinline__ int cell_of(float x0, float x1, float x2) {
    return (cell_coord(x0) * 16 + cell_coord(x1)) * 16 + cell_coord(x2);
}

// ---------------- pass 1: histogram (unmasked only) -------------------------
__global__ void k_hist(const float* __restrict__ x) {
    int p = blockIdx.x * blockDim.x + threadIdx.x;
    float x0 = x[3 * p + 0], x1 = x[3 * p + 1], x2 = x[3 * p + 2];
    if (!((fabsf(x0) < 1.5f) && (fabsf(x1) < 1.5f) && (fabsf(x2) < 1.5f))) return;
    atomicAdd(&g_count[cell_of(x0, x1, x2)], 1);
}

// ------ pass 2: shfl-scan + reset counts + build pass list (1 block) --------
__global__ void k_scan() {
    __shared__ int wsum[32];
    int t = threadIdx.x;
    int lane = t & 31, w = t >> 5;
    if (t == 0) { g_npass = 0; g_fetch = 0; }
    int b = t * 4;
    int4 cv = *(int4*)&g_count[b];
    *(int4*)&g_count[b] = make_int4(0, 0, 0, 0);
    int sum = cv.x + cv.y + cv.z + cv.w;
    int inc = sum;
    #pragma unroll
    for (int o = 1; o < 32; o <<= 1) {
        int v = __shfl_up_sync(0xFFFFFFFFu, inc, o);
        if (lane >= o) inc += v;
    }
    if (lane == 31) wsum[w] = inc;
    __syncthreads();
    if (w == 0) {
        int v = wsum[lane];
        int i = v;
        #pragma unroll
        for (int o = 1; o < 32; o <<= 1) {
            int u = __shfl_up_sync(0xFFFFFFFFu, i, o);
            if (lane >= o) i += u;
        }
        wsum[lane] = i - v;   // exclusive
    }
    __syncthreads();
    int excl = wsum[w] + inc - sum;
    int st[5];
    st[0] = excl;
    st[1] = excl + cv.x;
    st[2] = excl + cv.x + cv.y;
    st[3] = excl + cv.x + cv.y + cv.z;
    st[4] = excl + sum;
    g_start[b + 0] = st[0];
    g_start[b + 1] = st[1];
    g_start[b + 2] = st[2];
    g_start[b + 3] = st[3];
    if (t == 1023) g_start[NC] = st[4];

    // build 32-point pass list for this thread's 4 cells
    #pragma unroll
    for (int k = 0; k < 4; k++) {
        int c = b + k;
        g_cursor[c] = 0;
        int s = st[k];
        int cnt = st[k + 1] - s;
        if (cnt == 0) continue;
        int np = (cnt + 31) >> 5;
        int base = atomicAdd(&g_npass, np);
        for (int j = 0; j < np; j++) {
            int len = min(32, cnt - 32 * j);
            g_pass[base + j] = make_int2(s + 32 * j, c | (len << 16));
        }
    }
}

// ---------------- pass 3: scatter staged data / zero masked outputs ---------
__global__ void k_scatter(const float* __restrict__ x, const float* __restrict__ d,
                          float* __restrict__ out) {
    int p = blockIdx.x * blockDim.x + threadIdx.x;
    float x0 = x[3 * p + 0], x1 = x[3 * p + 1], x2 = x[3 * p + 2];
    bool mask = (fabsf(x0) < 1.5f) && (fabsf(x1) < 1.5f) && (fabsf(x2) < 1.5f);
    if (!mask) {
        out[3 * p + 0] = 0.0f;
        out[3 * p + 1] = 0.0f;
        out[3 * p + 2] = 0.0f;
        out[3 * NPTS + p] = 0.0f;
        return;
    }
    int cell = cell_of(x0, x1, x2);
    int pos = g_start[cell] + atomicAdd(&g_cursor[cell], 1);
    float d0 = d[3 * p + 0], d1 = d[3 * p + 1], d2 = d[3 * p + 2];
    g_pt[2 * pos + 0] = make_float4(x0, x1, x2, d0);
    g_pt[2 * pos + 1] = make_float4(d1, d2, __int_as_float(p), 0.0f);
}

// ---------------- fast sincos: Cody-Waite reduction + MUFU ------------------
__device__ __forceinline__ void fsincos(float a, float& sn, float& cs) {
    float k = rintf(a * 0.15915493667125702f);
    float r = fmaf(k, -6.2831854820251465f, a);
    r = fmaf(k, 1.7484556000744487e-7f, r);
    sn = __sinf(r);
    cs = __cosf(r);
}

// ---------------- cp.async helpers ------------------------------------------
__device__ __forceinline__ void cpa16(uint32_t saddr, const void* g) {
    asm volatile("cp.async.cg.shared.global [%0], [%1], 16;" :: "r"(saddr), "l"(g));
}
__device__ __forceinline__ void cpa4(uint32_t saddr, const void* g) {
    asm volatile("cp.async.ca.shared.global [%0], [%1], 4;" :: "r"(saddr), "l"(g));
}
__device__ __forceinline__ void cpa_commit() {
    asm volatile("cp.async.commit_group;");
}
__device__ __forceinline__ void cpa_wait0() {
    asm volatile("cp.async.wait_group 0;");
}
__device__ __forceinline__ void cpa_wait1() {
    asm volatile("cp.async.wait_group 1;");
}

template <int N4>
__device__ __forceinline__ void stage(uint32_t dst, const float4* __restrict__ src, int tid) {
    #pragma unroll
    for (int i = tid; i < N4; i += 32) cpa16(dst + 16u * i, src + i);
}

// ---------------- packed f32x2 primitives -----------------------------------
__device__ __forceinline__ void fma2(u64& a, u64 v, u64 w) {
    asm("fma.rn.f32x2 %0, %1, %2, %0;" : "+l"(a) : "l"(v), "l"(w));
}
__device__ __forceinline__ u64 pk2(float v) {
    u64 r; asm("mov.b64 %0, {%1, %1};" : "=l"(r) : "f"(v)); return r;
}
__device__ __forceinline__ float2 upk(u64 p) {
    float2 f; asm("mov.b64 {%0, %1}, %2;" : "=f"(f.x), "=f"(f.y) : "l"(p)); return f;
}

template <int NP2>
__device__ __forceinline__ void feedp(float v, const float* __restrict__ w, u64* acc) {
    u64 vv = pk2(v);
    const ulonglong2* wv = (const ulonglong2*)w;
    #pragma unroll
    for (int k = 0; k < NP2; k++) {
        ulonglong2 u = wv[k];
        fma2(acc[2 * k + 0], vv, u.x);
        fma2(acc[2 * k + 1], vv, u.y);
    }
}

// ------- pass 4: persistent blocks, work-steal one 32-point pass at a time --
__global__ void __launch_bounds__(32, 16) k_mlp(
    const float* __restrict__ w1, const float* __restrict__ b1,
    const float* __restrict__ w2, const float* __restrict__ b2,
    const float* __restrict__ w3, const float* __restrict__ b3,
    const float* __restrict__ w4, const float* __restrict__ b4,
    const float* __restrict__ w5, const float* __restrict__ b5,
    float* __restrict__ out)
{
    int tid = threadIdx.x;

    __shared__ __align__(16) float sbuf[BUFN];
    __shared__ __align__(16) float sb1[32];
    __shared__ __align__(16) float sb2[36];
    __shared__ __align__(16) float sb3[32];
    __shared__ __align__(16) float sb4[32];
    __shared__ __align__(16) float sb5[4];

    uint32_t sb = (uint32_t)__cvta_generic_to_shared(sbuf);
    int npass = g_npass;

    while (true) {
        int pid;
        if (tid == 0) pid = atomicAdd(&g_fetch, 1);
        pid = __shfl_sync(0xFFFFFFFFu, pid, 0);
        if (pid >= npass) break;

        int2 pe = g_pass[pid];
        int slot0 = pe.x;
        int cell = pe.y & 0xFFFF;
        int len = pe.y >> 16;

        const size_t c = (size_t)cell;
        const float4* w1v = (const float4*)(w1 + c * 2016);
        const float* w2r = w2 + c * 1056;
        const float4* w3v = (const float4*)(w3 + c * 1024);
        const float4* w4v = (const float4*)(w4 + c * 1888);
        const float* w5r = w5 + c * 96;

        // group 0: L1 weights; group 1: L2 weights (padded 33->36 on the fly)
        stage<504>(sb + OFF1 * 4, w1v, tid); cpa_commit();
        {
            uint32_t dst = sb + (OFF2 + tid * 36) * 4;
            const float* src = w2r + tid * 33;
            #pragma unroll
            for (int k = 0; k < 33; k++) cpa4(dst + 4u * k, src + k);
        }
        cpa_commit();

        // biases (regular LDG/STS, overlap with cp.async)
        sb1[tid] = b1[c * 32 + tid];
        sb3[tid] = b3[c * 32 + tid];
        sb4[tid] = b4[c * 32 + tid];
        sb2[tid] = b2[c * 33 + tid];
        if (tid == 0) sb2[32] = b2[c * 33 + 32];
        if (tid < 3) sb5[tid] = b5[c * 3 + tid];

        bool active = tid < len;
        int slot = slot0 + (active ? tid : (len - 1));
        float4 pa = g_pt[2 * slot + 0];
        float4 pb = g_pt[2 * slot + 1];
        float x0 = pa.x, x1 = pa.y, x2 = pa.z;
        float d0 = pa.w, d1 = pb.x, d2 = pb.y;
        int idx = __float_as_int(pb.z);

        cpa_wait1();
        __syncwarp();

        u64 P[17];          // packed accumulator pairs
        float Asc[33];      // unpacked activations

        // ---- layer 1: encode(x) [63] -> 32, relu ----
        {
            const float* sw1 = sbuf + OFF1;
            const u64* bp = (const u64*)sb1;
            #pragma unroll
            for (int k = 0; k < 16; k++) P[k] = bp[k];
            feedp<8>(x0, sw1 +  0, P);
            feedp<8>(x1, sw1 + 32, P);
            feedp<8>(x2, sw1 + 64, P);
            const float* wp = sw1 + 96;
            float s = 1.0f;
            #pragma unroll
            for (int j = 0; j < 10; j++) {
                float sn0, cs0, sn1, cs1, sn2, cs2;
                fsincos(s * x0, sn0, cs0);
                fsincos(s * x1, sn1, cs1);
                fsincos(s * x2, sn2, cs2);
                feedp<8>(sn0, wp, P); wp += 32;
                feedp<8>(sn1, wp, P); wp += 32;
                feedp<8>(sn2, wp, P); wp += 32;
                feedp<8>(cs0, wp, P); wp += 32;
                feedp<8>(cs1, wp, P); wp += 32;
                feedp<8>(cs2, wp, P); wp += 32;
                s *= 2.0f;
            }
            #pragma unroll
            for (int k = 0; k < 16; k++) {
                float2 f = upk(P[k]);
                Asc[2 * k + 0] = fmaxf(f.x, 0.0f);
                Asc[2 * k + 1] = fmaxf(f.y, 0.0f);
            }
        }

        cpa_wait0(); __syncwarp();
        stage<256>(sb + OFF3 * 4, w3v, tid); cpa_commit();   // prefetch L3

        // ---- layer 2: 32 -> 33 (rows padded to 36), relu; sigma = out[0] ----
        float sigma;
        {
            const float* sw2 = sbuf + OFF2;
            const u64* bp = (const u64*)sb2;
            #pragma unroll
            for (int k = 0; k < 16; k++) P[k] = bp[k];
            float a32 = sb2[32];
            #pragma unroll
            for (int i = 0; i < 32; i++) {
                const float* row = sw2 + i * 36;
                float v = Asc[i];
                feedp<8>(v, row, P);
                a32 = fmaf(v, row[32], a32);
            }
            #pragma unroll
            for (int k = 0; k < 16; k++) {
                float2 f = upk(P[k]);
                Asc[2 * k + 0] = fmaxf(f.x, 0.0f);
                Asc[2 * k + 1] = fmaxf(f.y, 0.0f);
            }
            Asc[32] = fmaxf(a32, 0.0f);
            sigma = Asc[0];
        }

        cpa_wait0(); __syncwarp();
        stage<472>(sb + OFF4 * 4, w4v, tid); cpa_commit();   // prefetch L4

        // ---- layer 3: 32 -> 32, linear (inputs Asc[1..32]) ----
        {
            const float* sw3 = sbuf + OFF3;
            const u64* bp = (const u64*)sb3;
            #pragma unroll
            for (int k = 0; k < 16; k++) P[k] = bp[k];
            #pragma unroll
            for (int i = 0; i < 32; i++) feedp<8>(Asc[i + 1], sw3 + i * 32, P);
            #pragma unroll
            for (int k = 0; k < 16; k++) {
                float2 f = upk(P[k]);
                Asc[2 * k + 0] = f.x;
                Asc[2 * k + 1] = f.y;
            }
        }

        cpa_wait0(); __syncwarp();
        // prefetch L5 (padded 3->4 on the fly; region overlaps old w2, done above)
        {
            uint32_t dst = sb + (OFF5 + tid * 4) * 4;
            const float* src = w5r + tid * 3;
            #pragma unroll
            for (int k = 0; k < 3; k++) cpa4(dst + 4u * k, src + k);
        }
        cpa_commit();

        // ---- layer 4: [32 | encode(d) 27] -> 32, relu ----
        {
            const float* sw4 = sbuf + OFF4;
            const u64* bp = (const u64*)sb4;
            #pragma unroll
            for (int k = 0; k < 16; k++) P[k] = bp[k];
            #pragma unroll
            for (int i = 0; i < 32; i++) feedp<8>(Asc[i], sw4 + i * 32, P);
            const float* wp = sw4 + 32 * 32;
            feedp<8>(d0, wp, P); wp += 32;
            feedp<8>(d1, wp, P); wp += 32;
            feedp<8>(d2, wp, P); wp += 32;
            float s = 1.0f;
            #pragma unroll
            for (int j = 0; j < 4; j++) {
                float sn0, cs0, sn1, cs1, sn2, cs2;
                fsincos(s * d0, sn0, cs0);
                fsincos(s * d1, sn1, cs1);
                fsincos(s * d2, sn2, cs2);
                feedp<8>(sn0, wp, P); wp += 32;
                feedp<8>(sn1, wp, P); wp += 32;
                feedp<8>(sn2, wp, P); wp += 32;
                feedp<8>(cs0, wp, P); wp += 32;
                feedp<8>(cs1, wp, P); wp += 32;
                feedp<8>(cs2, wp, P); wp += 32;
                s *= 2.0f;
            }
            #pragma unroll
            for (int k = 0; k < 16; k++) {
                float2 f = upk(P[k]);
                Asc[2 * k + 0] = fmaxf(f.x, 0.0f);
                Asc[2 * k + 1] = fmaxf(f.y, 0.0f);
            }
        }

        cpa_wait0(); __syncwarp();

        // ---- layer 5: 32 -> 3 (rows padded to 4), sigmoid ----
        float r0, r1, r2;
        {
            const float* sw5 = sbuf + OFF5;
            u64 r01;
            asm("mov.b64 %0, {%1, %2};" : "=l"(r01) : "f"(sb5[0]), "f"(sb5[1]));
            r2 = sb5[2];
            const ulonglong2* wv = (const ulonglong2*)sw5;
            #pragma unroll
            for (int i = 0; i < 32; i++) {
                ulonglong2 u = wv[i];
                float v = Asc[i];
                fma2(r01, pk2(v), u.x);
                r2 = fmaf(v, upk(u.y).x, r2);
            }
            float2 f = upk(r01);
            r0 = 1.0f / (1.0f + __expf(-f.x));
            r1 = 1.0f / (1.0f + __expf(-f.y));
            r2 = 1.0f / (1.0f + __expf(-r2));
        }

        if (active) {
            out[3 * idx + 0] = r0;
            out[3 * idx + 1] = r1;
            out[3 * idx + 2] = r2;
            out[3 * NPTS + idx] = sigma;
        }
        __syncwarp();   // all lanes done reading sbuf before next pass restages
    }
}

// ---------------- launch ----------------------------------------------------
extern "C" void kernel_launch(void* const* d_in, const int* in_sizes, int n_in,
                              void* d_out, int out_size) {
    const float* x  = (const float*)d_in[0];
    const float* dd = (const float*)d_in[1];
    const float* w1 = (const float*)d_in[2];
    const float* b1 = (const float*)d_in[3];
    const float* w2 = (const float*)d_in[4];
    const float* b2 = (const float*)d_in[5];
    const float* w3 = (const float*)d_in[6];
    const float* b3 = (const float*)d_in[7];
    const float* w4 = (const float*)d_in[8];
    const float* b4 = (const float*)d_in[9];
    const float* w5 = (const float*)d_in[10];
    const float* b5 = (const float*)d_in[11];
    float* out = (float*)d_out;

    k_hist<<<NPTS / 256, 256>>>(x);
    k_scan<<<1, 1024>>>();
    k_scatter<<<NPTS / 256, 256>>>(x, dd, out);
    k_mlp<<<NBLK, 32>>>(w1, b1, w2, b2, w3, b3, w4, b4, w5, b5, out);
}